// round 17
// baseline (speedup 1.0000x reference)
#include <cuda_runtime.h>
#include <cuda_bf16.h>
#include <cuda_fp16.h>
#include <cstdint>

#define NMAX 50000
#define EMAX 800000
#define KDIM 256
#define HC   128
#define H    4
#define C    32

// Static scratch (no allocations allowed in kernel_launch).
__device__ __align__(16) __half g_h[NMAX * HC];   // projected features, fp16
__device__ __align__(16) float g_asrc[NMAX * H];
// Packed per-node record: [0:4)=adst(4 heads), [4]=offs (int), [5]=cnt (int), [6:8) pad
__device__ __align__(32) float g_nodeD[NMAX * 8];
__device__ __align__(16) __nv_bfloat16 g_Bhi[KDIM * HC]; // pre-split weights
__device__ __align__(16) __nv_bfloat16 g_Blo[KDIM * HC];
__device__ int g_cnt[NMAX];   // in-degree; zeroed by scan (static-zero first run)
__device__ int g_cur[NMAX];   // CSR fill cursors
__device__ int g_psrc[EMAX];  // src node id, CSR slot order
__device__ int g_total;       // running block-offset counter (zeroed by agg)

// ---------------------------------------------------------------------------
// PTX helpers
// ---------------------------------------------------------------------------
__device__ __forceinline__ uint32_t s2u(const void* p) {
    uint32_t a;
    asm("{ .reg .u64 t; cvta.to.shared.u64 t, %1; cvt.u32.u64 %0, t; }"
        : "=r"(a) : "l"(p));
    return a;
}

#define LDSM4(r, addr)                                                        \
    asm volatile("ldmatrix.sync.aligned.m8n8.x4.shared.b16 {%0,%1,%2,%3}, [%4];" \
                 : "=r"((r)[0]), "=r"((r)[1]), "=r"((r)[2]), "=r"((r)[3])     \
                 : "r"(addr))

#define LDSM4T(r, addr)                                                       \
    asm volatile("ldmatrix.sync.aligned.m8n8.x4.trans.shared.b16 {%0,%1,%2,%3}, [%4];" \
                 : "=r"((r)[0]), "=r"((r)[1]), "=r"((r)[2]), "=r"((r)[3])     \
                 : "r"(addr))

#define MMA_BF16(c, a, b0, b1)                                                \
    asm volatile("mma.sync.aligned.m16n8k16.row.col.f32.bf16.bf16.f32 "       \
                 "{%0,%1,%2,%3}, {%4,%5,%6,%7}, {%8,%9}, {%0,%1,%2,%3};"      \
                 : "+f"((c)[0]), "+f"((c)[1]), "+f"((c)[2]), "+f"((c)[3])     \
                 : "r"((a)[0]), "r"((a)[1]), "r"((a)[2]), "r"((a)[3]),        \
                   "r"(b0), "r"(b1))

#define CP_ASYNC16(dst, src)                                                  \
    asm volatile("cp.async.ca.shared.global [%0], [%1], 16;"                  \
                 :: "r"(dst), "l"(src))
#define CP_COMMIT()  asm volatile("cp.async.commit_group;" ::: "memory")
#define CP_WAIT0()   asm volatile("cp.async.wait_group 0;" ::: "memory")

// Split pair (a,b) -> packed bf16x2 hi (lo16=a, hi16=b) and packed lo residue.
__device__ __forceinline__ void split2(float a, float b, uint32_t& hi, uint32_t& lo) {
    asm("cvt.rn.bf16x2.f32 %0, %1, %2;" : "=r"(hi) : "f"(b), "f"(a));
    float ahf = __uint_as_float(hi << 16);
    float bhf = __uint_as_float(hi & 0xFFFF0000u);
    float la = a - ahf, lb = b - bhf;
    asm("cvt.rn.bf16x2.f32 %0, %1, %2;" : "=r"(lo) : "f"(lb), "f"(la));
}

// ---------------------------------------------------------------------------
// Fused prep: pre-split weights into bf16 hi/lo planes (first 64 blocks' work)
// + in-degree histogram, 4 edges/thread (RED, no return).
// ---------------------------------------------------------------------------
__global__ void w2bf_hist(const float* __restrict__ w, const int* __restrict__ ei,
                          int e_cnt) {
    int idx = blockIdx.x * blockDim.x + threadIdx.x;
    if (idx < KDIM * HC / 2) {
        int k = (idx * 2) / HC;
        int nn = (idx * 2) % HC;
        float a = w[(nn >> 5) * (KDIM * C) + k * C + (nn & 31)];
        float b = w[((nn + 1) >> 5) * (KDIM * C) + k * C + ((nn + 1) & 31)];
        uint32_t hi, lo;
        split2(a, b, hi, lo);
        *(uint32_t*)&g_Bhi[idx * 2] = hi;
        *(uint32_t*)&g_Blo[idx * 2] = lo;
    }
    int e = idx * 4;
    if (e + 3 < e_cnt) {
        int4 dd = *(const int4*)&ei[e_cnt + e];
        atomicAdd(&g_cnt[dd.x], 1);
        atomicAdd(&g_cnt[dd.y], 1);
        atomicAdd(&g_cnt[dd.z], 1);
        atomicAdd(&g_cnt[dd.w], 1);
    } else {
        for (; e < e_cnt; e++) atomicAdd(&g_cnt[ei[e_cnt + e]], 1);
    }
}

// ---------------------------------------------------------------------------
// Single-pass scan: block-local Hillis-Steele + atomic global block offset.
// Writes offs + cnt into the node record, seeds fill cursors, and re-zeroes
// g_cnt for the next invocation.
// ---------------------------------------------------------------------------
__global__ void scan_kernel(int n) {
    __shared__ int sh[256];
    __shared__ int bOff;
    int t = threadIdx.x;
    int i = blockIdx.x * 256 + t;
    int v = (i < n) ? g_cnt[i] : 0;
    sh[t] = v;
    __syncthreads();
    #pragma unroll
    for (int off = 1; off < 256; off <<= 1) {
        int u = (t >= off) ? sh[t - off] : 0;
        __syncthreads();
        sh[t] += u;
        __syncthreads();
    }
    if (t == 255) bOff = atomicAdd(&g_total, sh[255]);
    __syncthreads();
    if (i < n) {
        int off = bOff + sh[t] - v;
        ((int*)g_nodeD)[i * 8 + 4] = off;
        ((int*)g_nodeD)[i * 8 + 5] = v;
        g_cur[i] = off;
        g_cnt[i] = 0;                   // prep next invocation
    }
}

// ---------------------------------------------------------------------------
// Block-specialized phase:
//  blocks [0,nGemm): tensor-core GEMM (bf16x3 fp32 emulation) + fused logits.
//  blocks [nGemm,..): CSR fill (4 edges/thread; depends only on the scan,
//    so it rides in the gemm's shadow instead of a serial launch slot).
// ---------------------------------------------------------------------------
__global__ void __launch_bounds__(256, 2)
gemm_tc(const float* __restrict__ Ain, const float* __restrict__ att,
        const int* __restrict__ ei, int M, int e_cnt, int nGemm) {
    __shared__ __align__(16) __nv_bfloat16 sA[2][2][128][24]; // [buf][hi/lo][m][k]
    __shared__ __align__(16) __nv_bfloat16 sB[2][2][16][136]; // [buf][hi/lo][k][n]

    if (blockIdx.x >= nGemm) {
        // ---- CSR fill tail blocks ----
        int e = ((blockIdx.x - nGemm) * blockDim.x + threadIdx.x) * 4;
        if (e + 3 < e_cnt) {
            int4 ss = *(const int4*)&ei[e];
            int4 dd = *(const int4*)&ei[e_cnt + e];
            int s0 = atomicAdd(&g_cur[dd.x], 1);
            int s1 = atomicAdd(&g_cur[dd.y], 1);
            int s2 = atomicAdd(&g_cur[dd.z], 1);
            int s3 = atomicAdd(&g_cur[dd.w], 1);
            g_psrc[s0] = ss.x;
            g_psrc[s1] = ss.y;
            g_psrc[s2] = ss.z;
            g_psrc[s3] = ss.w;
        } else {
            for (; e < e_cnt; e++) {
                int slot = atomicAdd(&g_cur[ei[e_cnt + e]], 1);
                g_psrc[slot] = ei[e];
            }
        }
        return;
    }

    const int t = threadIdx.x;
    const int blockRow = blockIdx.x * 128;
    const int warp = t >> 5, lane = t & 31;
    const int wm = warp >> 2, wn = warp & 3;     // wn == head
    const int rquad = lane & 15, chalf = lane >> 4;
    const int grp = lane >> 2, qd = lane & 3;

    float acc[4][2][2][4];
    #pragma unroll
    for (int mt = 0; mt < 4; mt++)
        #pragma unroll
        for (int g = 0; g < 2; g++)
            #pragma unroll
            for (int s = 0; s < 2; s++)
                #pragma unroll
                for (int i = 0; i < 4; i++) acc[mt][g][s][i] = 0.f;

    const int am = t >> 1, akq = (t & 1) * 8;        // A: row, k-offset(0/8)
    const int bk = t >> 4, bnq = (t & 15) * 8;       // B: k-row, n-offset
    const int agr = blockRow + am;
    const float* aBase = Ain + (long long)agr * KDIM + akq;

    auto stage = [&](int kc, int buf) {
        int kbase = kc * 16;
        int kg = kbase + bk;
        CP_ASYNC16(s2u(&sB[buf][0][bk][bnq]), &g_Bhi[kg * HC + bnq]);
        CP_ASYNC16(s2u(&sB[buf][1][bk][bnq]), &g_Blo[kg * HC + bnq]);
        CP_COMMIT();
        float4 f0 = make_float4(0.f, 0.f, 0.f, 0.f), f1 = f0;
        if (agr < M) {
            f0 = *(const float4*)(aBase + kbase);
            f1 = *(const float4*)(aBase + kbase + 4);
        }
        uint4 hi4, lo4;
        split2(f0.x, f0.y, hi4.x, lo4.x);
        split2(f0.z, f0.w, hi4.y, lo4.y);
        split2(f1.x, f1.y, hi4.z, lo4.z);
        split2(f1.z, f1.w, hi4.w, lo4.w);
        *(uint4*)&sA[buf][0][am][akq] = hi4;
        *(uint4*)&sA[buf][1][am][akq] = lo4;
    };

    stage(0, 0);
    CP_WAIT0();
    __syncthreads();

    uint32_t uA[2][2], uB[2][2];
    #pragma unroll
    for (int b = 0; b < 2; b++)
        #pragma unroll
        for (int p = 0; p < 2; p++) {
            uA[b][p] = s2u(&sA[b][p][0][0]);
            uB[b][p] = s2u(&sB[b][p][0][0]);
        }
    uint32_t aOff = ((wm * 64 + rquad) * 24 + chalf * 8) * 2;
    uint32_t bOff2 = (rquad * 136 + wn * 32 + chalf * 8) * 2;

    for (int kc = 0; kc < 16; kc++) {
        int buf = kc & 1;
        if (kc + 1 < 16) stage(kc + 1, buf ^ 1);

        uint32_t ah[4][4], al[4][4], bh[2][4], bl[2][4];
        #pragma unroll
        for (int mt = 0; mt < 4; mt++) {
            LDSM4(ah[mt], uA[buf][0] + aOff + mt * 16 * 24 * 2);
            LDSM4(al[mt], uA[buf][1] + aOff + mt * 16 * 24 * 2);
        }
        #pragma unroll
        for (int g = 0; g < 2; g++) {
            LDSM4T(bh[g], uB[buf][0] + bOff2 + g * 16 * 2);
            LDSM4T(bl[g], uB[buf][1] + bOff2 + g * 16 * 2);
        }
        #pragma unroll
        for (int mt = 0; mt < 4; mt++)
            #pragma unroll
            for (int g = 0; g < 2; g++)
                #pragma unroll
                for (int s = 0; s < 2; s++) {
                    float* c = acc[mt][g][s];
                    MMA_BF16(c, ah[mt], bh[g][s * 2], bh[g][s * 2 + 1]); // hi*hi
                    MMA_BF16(c, al[mt], bh[g][s * 2], bh[g][s * 2 + 1]); // lo*hi
                    MMA_BF16(c, ah[mt], bl[g][s * 2], bl[g][s * 2 + 1]); // hi*lo
                }
        CP_WAIT0();
        __syncthreads();
    }

    // ---- Epilogue: store h (fp16) + fused logits (from fp32 accumulators) ----
    float attS[2][2][2], attD[2][2][2];
    #pragma unroll
    for (int g = 0; g < 2; g++)
        #pragma unroll
        for (int s = 0; s < 2; s++)
            #pragma unroll
            for (int i = 0; i < 2; i++) {
                int cl = g * 16 + s * 8 + qd * 2 + i;
                attS[g][s][i] = __ldg(att + wn * (2 * C) + cl);
                attD[g][s][i] = __ldg(att + wn * (2 * C) + C + cl);
            }

    #pragma unroll
    for (int mt = 0; mt < 4; mt++) {
        int r0 = blockRow + wm * 64 + mt * 16 + grp;
        int r1 = r0 + 8;
        float s1a = 0.f, s1b = 0.f, s2a = 0.f, s2b = 0.f;
        #pragma unroll
        for (int g = 0; g < 2; g++)
            #pragma unroll
            for (int s = 0; s < 2; s++) {
                const float* c = acc[mt][g][s];
                int col = wn * 32 + g * 16 + s * 8 + qd * 2;
                if (r0 < M) *(__half2*)(g_h + r0 * HC + col) = __floats2half2_rn(c[0], c[1]);
                if (r1 < M) *(__half2*)(g_h + r1 * HC + col) = __floats2half2_rn(c[2], c[3]);
                s1a = fmaf(c[0], attS[g][s][0], fmaf(c[1], attS[g][s][1], s1a));
                s1b = fmaf(c[2], attS[g][s][0], fmaf(c[3], attS[g][s][1], s1b));
                s2a = fmaf(c[0], attD[g][s][0], fmaf(c[1], attD[g][s][1], s2a));
                s2b = fmaf(c[2], attD[g][s][0], fmaf(c[3], attD[g][s][1], s2b));
            }
        s1a += __shfl_xor_sync(0xffffffffu, s1a, 1);
        s1a += __shfl_xor_sync(0xffffffffu, s1a, 2);
        s1b += __shfl_xor_sync(0xffffffffu, s1b, 1);
        s1b += __shfl_xor_sync(0xffffffffu, s1b, 2);
        s2a += __shfl_xor_sync(0xffffffffu, s2a, 1);
        s2a += __shfl_xor_sync(0xffffffffu, s2a, 2);
        s2b += __shfl_xor_sync(0xffffffffu, s2b, 1);
        s2b += __shfl_xor_sync(0xffffffffu, s2b, 2);
        if (qd == 0) {
            if (r0 < M) { g_asrc[r0 * H + wn] = s1a; g_nodeD[r0 * 8 + wn] = s2a; }
            if (r1 < M) { g_asrc[r1 * H + wn] = s1b; g_nodeD[r1 * 8 + wn] = s2b; }
        }
    }
}

// ---------------------------------------------------------------------------
// Half-warp-paired gather aggregation: one warp per dst node; the two
// half-warps process two edges simultaneously (16 lanes x uint4 = full
// 128-ch fp16 row each). __launch_bounds__(256, 6) caps regs at 42 to hold
// 6 CTAs/SM (75% occupancy) with the reduced per-edge instruction stream.
// out[d] = (sum_e h[src_e]*alpha_e) / (sum_e alpha_e + eps) + bias
// ---------------------------------------------------------------------------
__global__ void __launch_bounds__(256, 6)
agg_kernel(float* __restrict__ out, const float* __restrict__ bias, int n) {
    int gid = blockIdx.x * blockDim.x + threadIdx.x;
    if (gid == 0) g_total = 0;          // prep next invocation
    int node = gid >> 5;
    if (node >= n) return;
    int lane = gid & 31;
    int half = lane >> 4;               // which edge of the pair
    int li = lane & 15;                 // covers channels [li*8, li*8+8)
    int hh = li >> 2;                   // head of this 8-channel slice
    const int* nd = (const int*)g_nodeD + node * 8;
    int beg = __ldg(nd + 4);
    int end = beg + __ldg(nd + 5);
    float adh = __ldg(&g_nodeD[node * 8 + hh]);
    float ac0 = 0.f, ac1 = 0.f, ac2 = 0.f, ac3 = 0.f;
    float ac4 = 0.f, ac5 = 0.f, ac6 = 0.f, ac7 = 0.f;
    float asum = 0.f;

    int i = beg;
    for (; i + 4 <= end; i += 4) {
        int sA_ = __ldg(&g_psrc[i + half]);
        int sB_ = __ldg(&g_psrc[i + 2 + half]);
        float lA = __ldg(&g_asrc[sA_ * 4 + hh]) + adh;
        float lB = __ldg(&g_asrc[sB_ * 4 + hh]) + adh;
        uint4 uA_ = __ldg((const uint4*)(g_h + sA_ * HC) + li);
        uint4 uB_ = __ldg((const uint4*)(g_h + sB_ * HC) + li);
        float aA = __expf(lA > 0.f ? lA : 0.2f * lA);
        float aB = __expf(lB > 0.f ? lB : 0.2f * lB);
        asum += aA + aB;
        float2 p;
        p = __half22float2(*(__half2*)&uA_.x); ac0 = fmaf(p.x, aA, ac0); ac1 = fmaf(p.y, aA, ac1);
        p = __half22float2(*(__half2*)&uA_.y); ac2 = fmaf(p.x, aA, ac2); ac3 = fmaf(p.y, aA, ac3);
        p = __half22float2(*(__half2*)&uA_.z); ac4 = fmaf(p.x, aA, ac4); ac5 = fmaf(p.y, aA, ac5);
        p = __half22float2(*(__half2*)&uA_.w); ac6 = fmaf(p.x, aA, ac6); ac7 = fmaf(p.y, aA, ac7);
        p = __half22float2(*(__half2*)&uB_.x); ac0 = fmaf(p.x, aB, ac0); ac1 = fmaf(p.y, aB, ac1);
        p = __half22float2(*(__half2*)&uB_.y); ac2 = fmaf(p.x, aB, ac2); ac3 = fmaf(p.y, aB, ac3);
        p = __half22float2(*(__half2*)&uB_.z); ac4 = fmaf(p.x, aB, ac4); ac5 = fmaf(p.y, aB, ac5);
        p = __half22float2(*(__half2*)&uB_.w); ac6 = fmaf(p.x, aB, ac6); ac7 = fmaf(p.y, aB, ac7);
    }
    for (; i < end; i += 2) {
        int j = i + half;
        bool valid = j < end;
        int jj = valid ? j : i;
        int s = __ldg(&g_psrc[jj]);
        float l = __ldg(&g_asrc[s * 4 + hh]) + adh;
        uint4 u = __ldg((const uint4*)(g_h + s * HC) + li);
        float a = valid ? __expf(l > 0.f ? l : 0.2f * l) : 0.f;
        asum += a;
        float2 p;
        p = __half22float2(*(__half2*)&u.x); ac0 = fmaf(p.x, a, ac0); ac1 = fmaf(p.y, a, ac1);
        p = __half22float2(*(__half2*)&u.y); ac2 = fmaf(p.x, a, ac2); ac3 = fmaf(p.y, a, ac3);
        p = __half22float2(*(__half2*)&u.z); ac4 = fmaf(p.x, a, ac4); ac5 = fmaf(p.y, a, ac5);
        p = __half22float2(*(__half2*)&u.w); ac6 = fmaf(p.x, a, ac6); ac7 = fmaf(p.y, a, ac7);
    }

    // Combine the two half-warps (same channels, disjoint edge subsets).
    asum += __shfl_xor_sync(0xffffffffu, asum, 16);
    ac0 += __shfl_xor_sync(0xffffffffu, ac0, 16);
    ac1 += __shfl_xor_sync(0xffffffffu, ac1, 16);
    ac2 += __shfl_xor_sync(0xffffffffu, ac2, 16);
    ac3 += __shfl_xor_sync(0xffffffffu, ac3, 16);
    ac4 += __shfl_xor_sync(0xffffffffu, ac4, 16);
    ac5 += __shfl_xor_sync(0xffffffffu, ac5, 16);
    ac6 += __shfl_xor_sync(0xffffffffu, ac6, 16);
    ac7 += __shfl_xor_sync(0xffffffffu, ac7, 16);

    if (half == 0) {
        float r = __frcp_rn(asum + 1e-16f);
        const float4 b0 = *(const float4*)(bias + li * 8);
        const float4 b1 = *(const float4*)(bias + li * 8 + 4);
        float* op = out + node * HC + li * 8;
        *(float4*)op = make_float4(fmaf(ac0, r, b0.x), fmaf(ac1, r, b0.y),
                                   fmaf(ac2, r, b0.z), fmaf(ac3, r, b0.w));
        *(float4*)(op + 4) = make_float4(fmaf(ac4, r, b1.x), fmaf(ac5, r, b1.y),
                                         fmaf(ac6, r, b1.z), fmaf(ac7, r, b1.w));
    }
}

// ---------------------------------------------------------------------------
extern "C" void kernel_launch(void* const* d_in, const int* in_sizes, int n_in,
                              void* d_out, int out_size) {
    const float* x    = (const float*)d_in[0];
    const int*   ei   = (const int*)d_in[1];
    const float* w    = (const float*)d_in[2];
    const float* att  = (const float*)d_in[3];
    const float* bias = (const float*)d_in[4];
    float* out = (float*)d_out;

    int n     = in_sizes[0] / KDIM;   // 50000
    int e_cnt = in_sizes[1] / 2;      // 800000

    int nPrep = ((e_cnt + 3) / 4 + 255) / 256;
    if (nPrep < (KDIM * HC / 2 + 255) / 256) nPrep = (KDIM * HC / 2 + 255) / 256;
    w2bf_hist<<<nPrep, 256>>>(w, ei, e_cnt);
    scan_kernel<<<(n + 255) / 256, 256>>>(n);
    int nGemm = (n + 127) / 128;
    int nFill = ((e_cnt + 3) / 4 + 255) / 256;
    gemm_tc<<<nGemm + nFill, 256>>>(x, att, ei, n, e_cnt, nGemm);
    agg_kernel<<<(n * 32 + 255) / 256, 256>>>(out, bias, n);
}